// round 2
// baseline (speedup 1.0000x reference)
#include <cuda_runtime.h>
#include <cstddef>

#define N_USER 100000
#define N_ITEM 100000
#define N_EDGE 1000000
#define D      64

// degree scratch: [0, N_USER) = user degrees, [N_USER, N_USER+N_ITEM) = item degrees
__device__ float g_deg[N_USER + N_ITEM];

// ---------------------------------------------------------------------------
// Zero the output (h_user | h_item) and the degree scratch.
// ---------------------------------------------------------------------------
__global__ void zero_kernel(float4* __restrict__ out4) {
    int i = blockIdx.x * blockDim.x + threadIdx.x;
    const int n4 = (N_USER + N_ITEM) * D / 4;        // 3.2M float4
    if (i < n4) out4[i] = make_float4(0.f, 0.f, 0.f, 0.f);
    if (i < N_USER + N_ITEM) g_deg[i] = 0.f;
}

// ---------------------------------------------------------------------------
// Edge scatter: 16 threads per edge, each handles one float4 (4 of 64 dims).
// out[dst] += feat[src]   (red.global.add.v4.f32, no return value)
// g_deg[deg_off + dst] += 1   (lane 0 only)
// ---------------------------------------------------------------------------
__global__ void scatter_kernel(const float* __restrict__ feat,
                               const int*   __restrict__ src,
                               const int*   __restrict__ dst,
                               float*       __restrict__ out,
                               int deg_off) {
    int t = blockIdx.x * blockDim.x + threadIdx.x;
    int e = t >> 4;
    if (e >= N_EDGE) return;
    int lane = t & 15;

    int s = __ldg(src + e);
    int d = __ldg(dst + e);

    const float4 v = __ldg(reinterpret_cast<const float4*>(feat + (size_t)s * D) + lane);
    float* p = out + (size_t)d * D + lane * 4;

    asm volatile("red.global.add.v4.f32 [%0], {%1,%2,%3,%4};"
                 :: "l"(p), "f"(v.x), "f"(v.y), "f"(v.z), "f"(v.w)
                 : "memory");

    if (lane == 0) atomicAdd(&g_deg[deg_off + d], 1.0f);
}

// ---------------------------------------------------------------------------
// In-place per-row transform: y = (deg>0) ? (W @ x) / deg + b : 0
// One thread per row; W^T staged in shared memory (broadcast LDS.128 reads).
// ---------------------------------------------------------------------------
__global__ __launch_bounds__(256) void transform_kernel(float* __restrict__ io,
                                                        const float* __restrict__ W,
                                                        const float* __restrict__ b,
                                                        int deg_off, int n_rows) {
    __shared__ float Wt[D * D];   // Wt[k*D + j] = W[j*D + k]
    __shared__ float bs[D];

    int tid = threadIdx.x;
    for (int i = tid; i < D * D; i += 256) {
        int j = i >> 6, k = i & 63;
        Wt[k * D + j] = W[i];
    }
    if (tid < D) bs[tid] = b[tid];
    __syncthreads();

    int row = blockIdx.x * 256 + tid;
    if (row >= n_rows) return;

    float* x = io + (size_t)row * D;

    float acc[D];
#pragma unroll
    for (int j = 0; j < D; j++) acc[j] = 0.f;

#pragma unroll 1
    for (int k4 = 0; k4 < D / 4; k4++) {
        float4 xv = *reinterpret_cast<const float4*>(x + k4 * 4);
        float xs[4] = {xv.x, xv.y, xv.z, xv.w};
#pragma unroll
        for (int kk = 0; kk < 4; kk++) {
            float xk = xs[kk];
            int k = k4 * 4 + kk;
#pragma unroll
            for (int j4 = 0; j4 < D / 4; j4++) {
                float4 wv = *reinterpret_cast<const float4*>(Wt + k * D + j4 * 4);
                acc[j4 * 4 + 0] += xk * wv.x;
                acc[j4 * 4 + 1] += xk * wv.y;
                acc[j4 * 4 + 2] += xk * wv.z;
                acc[j4 * 4 + 3] += xk * wv.w;
            }
        }
    }

    float dg  = g_deg[deg_off + row];
    float inv = dg > 0.f ? 1.f / dg : 0.f;
    float bm  = dg > 0.f ? 1.f : 0.f;

#pragma unroll
    for (int j4 = 0; j4 < D / 4; j4++) {
        float4 y;
        y.x = acc[j4 * 4 + 0] * inv + bs[j4 * 4 + 0] * bm;
        y.y = acc[j4 * 4 + 1] * inv + bs[j4 * 4 + 1] * bm;
        y.z = acc[j4 * 4 + 2] * inv + bs[j4 * 4 + 2] * bm;
        y.w = acc[j4 * 4 + 3] * inv + bs[j4 * 4 + 3] * bm;
        *reinterpret_cast<float4*>(x + j4 * 4) = y;
    }
}

// ---------------------------------------------------------------------------
// Launch
// ---------------------------------------------------------------------------
extern "C" void kernel_launch(void* const* d_in, const int* in_sizes, int n_in,
                              void* d_out, int out_size) {
    const float* feat_user = (const float*)d_in[0];
    const float* feat_item = (const float*)d_in[1];
    const int*   src_clicks = (const int*)d_in[2];   // user ids
    const int*   dst_clicks = (const int*)d_in[3];   // item ids
    const int*   src_cb     = (const int*)d_in[4];   // item ids
    const int*   dst_cb     = (const int*)d_in[5];   // user ids
    const float* W_clicks   = (const float*)d_in[6];
    const float* b_clicks   = (const float*)d_in[7];
    const float* W_cb       = (const float*)d_in[8];
    const float* b_cb       = (const float*)d_in[9];

    float* out    = (float*)d_out;
    float* h_user = out;                           // [N_USER, D]
    float* h_item = out + (size_t)N_USER * D;      // [N_ITEM, D]

    // 1) zero output + degree scratch
    {
        const int n4 = (N_USER + N_ITEM) * D / 4;
        zero_kernel<<<(n4 + 255) / 256, 256>>>((float4*)out);
    }

    // 2) scatter raw features along edges (segment-sum + degree count)
    {
        const int threads = N_EDGE * 16;
        dim3 grid((threads + 255) / 256);
        // relation clicks: user feats -> item nodes (item degrees at offset N_USER)
        scatter_kernel<<<grid, 256>>>(feat_user, src_clicks, dst_clicks, h_item, N_USER);
        // relation clicked_by: item feats -> user nodes (user degrees at offset 0)
        scatter_kernel<<<grid, 256>>>(feat_item, src_cb, dst_cb, h_user, 0);
    }

    // 3) in-place linear + mean-normalize + zero-degree mask
    transform_kernel<<<(N_USER + 255) / 256, 256>>>(h_user, W_cb, b_cb, 0, N_USER);
    transform_kernel<<<(N_ITEM + 255) / 256, 256>>>(h_item, W_clicks, b_clicks, N_USER, N_ITEM);
}

// round 5
// speedup vs baseline: 1.0596x; 1.0596x over previous
#include <cuda_runtime.h>
#include <cstddef>

#define N_USER 100000
#define N_ITEM 100000
#define N_EDGE 1000000
#define D      64
#define NT     (N_USER + N_ITEM)

// ---------------------------------------------------------------------------
// Scratch (static device globals — no allocation allowed)
// deg/off/cnt regions: [0, N_USER) = user dsts, [N_USER, NT) = item dsts
// elist: relation A (dst=item) in [0, N_EDGE), relation B (dst=user) in [N_EDGE, 2*N_EDGE)
// ---------------------------------------------------------------------------
__device__ int g_deg[NT];
__device__ int g_off[NT];
__device__ int g_cnt[NT];
__device__ int g_elist[2 * N_EDGE];
__device__ int g_cursor[2];

// packed f32x2 helpers
__device__ __forceinline__ unsigned long long ffma2(unsigned long long a,
                                                    unsigned long long b,
                                                    unsigned long long c) {
    unsigned long long d;
    asm("fma.rn.f32x2 %0, %1, %2, %3;" : "=l"(d) : "l"(a), "l"(b), "l"(c));
    return d;
}
__device__ __forceinline__ unsigned long long pack2(float a) {
    unsigned long long r;
    asm("mov.b64 %0, {%1, %1};" : "=l"(r) : "f"(a));
    return r;
}
__device__ __forceinline__ void unpack2(unsigned long long v, float& lo, float& hi) {
    asm("mov.b64 {%0, %1}, %2;" : "=f"(lo), "=f"(hi) : "l"(v));
}

// ---------------------------------------------------------------------------
// 1) zero metadata
// ---------------------------------------------------------------------------
__global__ void zero_meta_kernel() {
    int i = blockIdx.x * blockDim.x + threadIdx.x;
    if (i < NT) { g_deg[i] = 0; g_cnt[i] = 0; }
    if (i < 2) g_cursor[i] = 0;
}

// ---------------------------------------------------------------------------
// 2) degree count (both relations fused)
// ---------------------------------------------------------------------------
__global__ void count_kernel(const int* __restrict__ dst_item,   // dst_clicks (item ids)
                             const int* __restrict__ dst_user) { // dst_clicked_by (user ids)
    int e = blockIdx.x * blockDim.x + threadIdx.x;
    if (e >= N_EDGE) return;
    atomicAdd(&g_deg[N_USER + __ldg(dst_item + e)], 1);
    atomicAdd(&g_deg[__ldg(dst_user + e)], 1);
}

// ---------------------------------------------------------------------------
// 3) segment offsets: per-block scan + bump allocator (segment order irrelevant)
// ---------------------------------------------------------------------------
__global__ __launch_bounds__(256) void offsets_kernel(int base, int n, int rel) {
    int tid = threadIdx.x;
    int i = blockIdx.x * 256 + tid;
    int lane = tid & 31, wid = tid >> 5;

    int v = (i < n) ? g_deg[base + i] : 0;

    // warp inclusive scan
    int x = v;
#pragma unroll
    for (int s = 1; s < 32; s <<= 1) {
        int y = __shfl_up_sync(0xFFFFFFFFu, x, s);
        if (lane >= s) x += y;
    }

    __shared__ int wsum[8];
    __shared__ int blockBase;
    if (lane == 31) wsum[wid] = x;
    __syncthreads();

    if (wid == 0) {
        int s = (lane < 8) ? wsum[lane] : 0;
#pragma unroll
        for (int d2 = 1; d2 < 8; d2 <<= 1) {
            int y = __shfl_up_sync(0xFFFFFFFFu, s, d2);
            if (lane >= d2) s += y;
        }
        if (lane < 8) wsum[lane] = s;              // inclusive warp sums
        if (lane == 7) blockBase = atomicAdd(&g_cursor[rel], s);
    }
    __syncthreads();

    if (i < n) {
        int warpBase = (wid > 0) ? wsum[wid - 1] : 0;
        g_off[base + i] = blockBase + warpBase + (x - v);   // exclusive within block
    }
}

// ---------------------------------------------------------------------------
// 4) fill edge lists (both relations fused)
// ---------------------------------------------------------------------------
__global__ void fill_kernel(const int* __restrict__ src_clicks,
                            const int* __restrict__ dst_clicks,
                            const int* __restrict__ src_cb,
                            const int* __restrict__ dst_cb) {
    int e = blockIdx.x * blockDim.x + threadIdx.x;
    if (e >= N_EDGE) return;
    {   // relation A: user -> item (dst region offset N_USER, elist region 0)
        int d = N_USER + __ldg(dst_clicks + e);
        int p = atomicAdd(&g_cnt[d], 1);
        g_elist[__ldg(&g_off[d]) + p] = __ldg(src_clicks + e);
    }
    {   // relation B: item -> user (dst region 0, elist region N_EDGE)
        int d = __ldg(dst_cb + e);
        int p = atomicAdd(&g_cnt[d], 1);
        g_elist[N_EDGE + __ldg(&g_off[d]) + p] = __ldg(src_cb + e);
    }
}

// ---------------------------------------------------------------------------
// 5) gather + mean: one warp per dst, lane owns 2 dims (float2), coalesced rows.
//    4-way edge unroll for MLP.
// ---------------------------------------------------------------------------
__global__ __launch_bounds__(256) void gather_kernel(const float* __restrict__ feat,
                                                     float* __restrict__ out,
                                                     int deg_off, int elist_base,
                                                     int n_dst) {
    int w = (blockIdx.x * 256 + threadIdx.x) >> 5;
    int lane = threadIdx.x & 31;
    if (w >= n_dst) return;

    int deg = __ldg(&g_deg[deg_off + w]);
    const int* el = g_elist + elist_base + __ldg(&g_off[deg_off + w]);

    float ax = 0.f, ay = 0.f;
    int e = 0;
    for (; e + 4 <= deg; e += 4) {
        int s0 = __ldg(el + e);
        int s1 = __ldg(el + e + 1);
        int s2 = __ldg(el + e + 2);
        int s3 = __ldg(el + e + 3);
        float2 v0 = __ldg(reinterpret_cast<const float2*>(feat + (size_t)s0 * D) + lane);
        float2 v1 = __ldg(reinterpret_cast<const float2*>(feat + (size_t)s1 * D) + lane);
        float2 v2 = __ldg(reinterpret_cast<const float2*>(feat + (size_t)s2 * D) + lane);
        float2 v3 = __ldg(reinterpret_cast<const float2*>(feat + (size_t)s3 * D) + lane);
        ax += (v0.x + v1.x) + (v2.x + v3.x);
        ay += (v0.y + v1.y) + (v2.y + v3.y);
    }
    for (; e < deg; e++) {
        int s0 = __ldg(el + e);
        float2 v0 = __ldg(reinterpret_cast<const float2*>(feat + (size_t)s0 * D) + lane);
        ax += v0.x;
        ay += v0.y;
    }

    float inv = deg > 0 ? 1.f / (float)deg : 0.f;
    float2 r; r.x = ax * inv; r.y = ay * inv;
    reinterpret_cast<float2*>(out + (size_t)w * D)[lane] = r;
}

// ---------------------------------------------------------------------------
// 6) in-place transform: y = (deg>0) ? W @ x + b : 0   (x is already the mean)
//    packed f32x2 FMA, W^T broadcast from shared
// ---------------------------------------------------------------------------
__global__ __launch_bounds__(256) void transform_kernel(float* __restrict__ io,
                                                        const float* __restrict__ W,
                                                        const float* __restrict__ b,
                                                        int deg_off, int n_rows) {
    __shared__ __align__(16) float Wt[D * D];   // Wt[k*D + j] = W[j*D + k]
    __shared__ float bs[D];

    int tid = threadIdx.x;
    for (int i = tid; i < D * D; i += 256) {
        int j = i >> 6, k = i & 63;
        Wt[k * D + j] = W[i];
    }
    if (tid < D) bs[tid] = b[tid];
    __syncthreads();

    int row = blockIdx.x * 256 + tid;
    if (row >= n_rows) return;

    float* x = io + (size_t)row * D;

    unsigned long long acc[D / 2];
#pragma unroll
    for (int j = 0; j < D / 2; j++) acc[j] = 0ull;

#pragma unroll 1
    for (int k4 = 0; k4 < D / 4; k4++) {
        float4 xv = *reinterpret_cast<const float4*>(x + k4 * 4);
        float xs[4] = {xv.x, xv.y, xv.z, xv.w};
#pragma unroll
        for (int kk = 0; kk < 4; kk++) {
            unsigned long long xk2 = pack2(xs[kk]);
            const ulonglong2* wrow =
                reinterpret_cast<const ulonglong2*>(Wt + (k4 * 4 + kk) * D);
#pragma unroll
            for (int j4 = 0; j4 < D / 4; j4++) {
                ulonglong2 wv = wrow[j4];                    // 4 W values (2 pairs)
                acc[2 * j4 + 0] = ffma2(xk2, wv.x, acc[2 * j4 + 0]);
                acc[2 * j4 + 1] = ffma2(xk2, wv.y, acc[2 * j4 + 1]);
            }
        }
    }

    int dg = __ldg(&g_deg[deg_off + row]);
    float bm = dg > 0 ? 1.f : 0.f;   // mask bias for zero-degree rows

#pragma unroll
    for (int j2 = 0; j2 < D / 2; j2++) {
        float lo, hi;
        unpack2(acc[j2], lo, hi);
        float2 y;
        y.x = lo + bs[2 * j2 + 0] * bm;
        y.y = hi + bs[2 * j2 + 1] * bm;
        reinterpret_cast<float2*>(x)[j2] = y;
    }
}

// ---------------------------------------------------------------------------
// Launch
// ---------------------------------------------------------------------------
extern "C" void kernel_launch(void* const* d_in, const int* in_sizes, int n_in,
                              void* d_out, int out_size) {
    const float* feat_user  = (const float*)d_in[0];
    const float* feat_item  = (const float*)d_in[1];
    const int*   src_clicks = (const int*)d_in[2];   // user ids
    const int*   dst_clicks = (const int*)d_in[3];   // item ids
    const int*   src_cb     = (const int*)d_in[4];   // item ids
    const int*   dst_cb     = (const int*)d_in[5];   // user ids
    const float* W_clicks   = (const float*)d_in[6];
    const float* b_clicks   = (const float*)d_in[7];
    const float* W_cb       = (const float*)d_in[8];
    const float* b_cb       = (const float*)d_in[9];

    float* out    = (float*)d_out;
    float* h_user = out;                           // [N_USER, D]
    float* h_item = out + (size_t)N_USER * D;      // [N_ITEM, D]

    // 1) zero metadata (deg/cnt/cursors)
    zero_meta_kernel<<<(NT + 255) / 256, 256>>>();

    // 2) degree count (both relations)
    count_kernel<<<(N_EDGE + 255) / 256, 256>>>(dst_clicks, dst_cb);

    // 3) segment offsets (bump-allocated, per relation)
    offsets_kernel<<<(N_ITEM + 255) / 256, 256>>>(N_USER, N_ITEM, 0); // item dsts
    offsets_kernel<<<(N_USER + 255) / 256, 256>>>(0,      N_USER, 1); // user dsts

    // 4) fill edge lists
    fill_kernel<<<(N_EDGE + 255) / 256, 256>>>(src_clicks, dst_clicks, src_cb, dst_cb);

    // 5) gather + mean (warp per dst)
    {
        int blkA = (N_ITEM * 32 + 255) / 256;
        int blkB = (N_USER * 32 + 255) / 256;
        gather_kernel<<<blkA, 256>>>(feat_user, h_item, N_USER, 0,      N_ITEM);
        gather_kernel<<<blkB, 256>>>(feat_item, h_user, 0,      N_EDGE, N_USER);
    }

    // 6) in-place transform
    transform_kernel<<<(N_USER + 255) / 256, 256>>>(h_user, W_cb, b_cb, 0, N_USER);
    transform_kernel<<<(N_ITEM + 255) / 256, 256>>>(h_item, W_clicks, b_clicks, N_USER, N_ITEM);
}